// round 1
// baseline (speedup 1.0000x reference)
#include <cuda_runtime.h>

#define NLAYERS 5

// tanh via ex2 + rcp:  tanh(y) = 1 - 2/(exp(2y)+1)
// Saturates correctly: y->+inf: e=inf -> rcp=0 -> 1 ; y->-inf: e=0 -> 1-2 = -1
__device__ __forceinline__ float fast_tanh(float y) {
    float e;
    asm("ex2.approx.f32 %0, %1;" : "=f"(e) : "f"(y * 2.8853900817779268f)); // 2*log2(e)
    float r;
    asm("rcp.approx.f32 %0, %1;" : "=f"(r) : "f"(e + 1.0f));
    return fmaf(-2.0f, r, 1.0f);
}

// sigmoid(z) = 1/(1+exp(-z))
__device__ __forceinline__ float fast_sigmoid(float z) {
    float e;
    asm("ex2.approx.f32 %0, %1;" : "=f"(e) : "f"(-z * 1.4426950408889634f)); // log2(e)
    float r;
    asm("rcp.approx.f32 %0, %1;" : "=f"(r) : "f"(e + 1.0f));
    return r;
}

__global__ __launch_bounds__(256)
void fraud_kernel(const float4* __restrict__ data,
                  const float* __restrict__ Wc, const float* __restrict__ bc,
                  const float* __restrict__ Wl, const float* __restrict__ bl,
                  const float* __restrict__ scale, const float* __restrict__ shift,
                  const float* __restrict__ Wf, const float* __restrict__ bf,
                  float* __restrict__ out, int B)
{
    // ---- load all params into registers once per thread (uniform, L1-hit) ----
    float wc0 = __ldg(Wc + 0), wc1 = __ldg(Wc + 1);
    float wc2 = __ldg(Wc + 2), wc3 = __ldg(Wc + 3);
    float bcv = __ldg(bc);

    float w00[NLAYERS], w01[NLAYERS], w10[NLAYERS], w11[NLAYERS];
    float b0[NLAYERS], b1[NLAYERS], s0[NLAYERS], s1[NLAYERS], h0[NLAYERS], h1[NLAYERS];
#pragma unroll
    for (int l = 0; l < NLAYERS; l++) {
        w00[l] = __ldg(Wl + 4 * l + 0);
        w01[l] = __ldg(Wl + 4 * l + 1);
        w10[l] = __ldg(Wl + 4 * l + 2);
        w11[l] = __ldg(Wl + 4 * l + 3);
        b0[l]  = __ldg(bl + 2 * l + 0);
        b1[l]  = __ldg(bl + 2 * l + 1);
        s0[l]  = __ldg(scale + 2 * l + 0);
        s1[l]  = __ldg(scale + 2 * l + 1);
        h0[l]  = __ldg(shift + 2 * l + 0);
        h1[l]  = __ldg(shift + 2 * l + 1);
    }
    float wf0 = __ldg(Wf + 0), wf1 = __ldg(Wf + 1);
    float bfv = __ldg(bf);

    const int stride = gridDim.x * blockDim.x;
    for (int i = blockIdx.x * blockDim.x + threadIdx.x; i < B; i += stride) {
        // one 2x2 patch = one float4, streaming (no reuse)
        float4 d = __ldcs(data + i);

        // conv-as-dot + bias, then sigmoid; input to chain is [s, 0]
        float z = fmaf(d.x, wc0, fmaf(d.y, wc1, fmaf(d.z, wc2, fmaf(d.w, wc3, bcv))));
        float x0 = fast_sigmoid(z);
        float x1 = 0.0f;

#pragma unroll
        for (int l = 0; l < NLAYERS; l++) {
            float y0 = fmaf(x0, w00[l], fmaf(x1, w01[l], b0[l]));
            float y1 = fmaf(x0, w10[l], fmaf(x1, w11[l], b1[l]));
            x0 = fmaf(fast_tanh(y0), s0[l], h0[l]);
            x1 = fmaf(fast_tanh(y1), s1[l], h1[l]);
        }

        float o = fmaf(x0, wf0, fmaf(x1, wf1, bfv));
        __stcs(out + i, o);
    }
}

extern "C" void kernel_launch(void* const* d_in, const int* in_sizes, int n_in,
                              void* d_out, int out_size)
{
    const float4* data  = (const float4*)d_in[0];
    const float*  Wc    = (const float*)d_in[1];
    const float*  bc    = (const float*)d_in[2];
    const float*  Wl    = (const float*)d_in[3];
    const float*  bl    = (const float*)d_in[4];
    const float*  scale = (const float*)d_in[5];
    const float*  shift = (const float*)d_in[6];
    const float*  Wf    = (const float*)d_in[7];
    const float*  bf    = (const float*)d_in[8];
    float* out = (float*)d_out;

    const int B = in_sizes[0] / 4;          // 4 floats per patch

    const int threads = 256;
    // ~8 patches per thread to amortize the 58 scalar param loads
    int blocks = (B + threads * 8 - 1) / (threads * 8);
    if (blocks < 1) blocks = 1;

    fraud_kernel<<<blocks, threads>>>(data, Wc, bc, Wl, bl, scale, shift, Wf, bf, out, B);
}

// round 2
// speedup vs baseline: 1.2675x; 1.2675x over previous
#include <cuda_runtime.h>

#define PPT 8        // patches per thread
#define THREADS 256

// tanh via ex2 + rcp:  tanh(y) = 1 - 2/(exp(2y)+1)
// Saturates correctly at +/-inf. abs err ~1e-7.
__device__ __forceinline__ float fast_tanh(float y) {
    float e;
    asm("ex2.approx.f32 %0, %1;" : "=f"(e) : "f"(y * 2.8853900817779268f)); // 2*log2(e)
    float r;
    asm("rcp.approx.f32 %0, %1;" : "=f"(r) : "f"(e + 1.0f));
    return fmaf(-2.0f, r, 1.0f);
}

// sigmoid(z) = 1/(1+exp(-z))
__device__ __forceinline__ float fast_sigmoid(float z) {
    float e;
    asm("ex2.approx.f32 %0, %1;" : "=f"(e) : "f"(-z * 1.4426950408889634f)); // log2(e)
    float r;
    asm("rcp.approx.f32 %0, %1;" : "=f"(r) : "f"(e + 1.0f));
    return r;
}

__global__ __launch_bounds__(THREADS)
void fraud_kernel(const float4* __restrict__ data,
                  const float* __restrict__ Wc, const float* __restrict__ bc,
                  const float* __restrict__ Wl, const float* __restrict__ bl,
                  const float* __restrict__ scale, const float* __restrict__ shift,
                  const float* __restrict__ Wf, const float* __restrict__ bf,
                  float* __restrict__ out, int B)
{
    // ================= parameter folding (uniform, once per thread) =================
    // Chain:  t_l = tanh(y_l);  x_l = t_l*sc_l + sh_l;  y_{l+1} = W_{l+1} x_l + b_{l+1}
    // Fold:   y_{l+1} = (W_{l+1} diag(sc_l)) t_l + (b_{l+1} + W_{l+1} sh_l)
    // Layer 0 input is [sigmoid, 0] -> only first column of W_0 matters.

    const float wc0 = __ldg(Wc + 0), wc1 = __ldg(Wc + 1);
    const float wc2 = __ldg(Wc + 2), wc3 = __ldg(Wc + 3);
    const float bcv = __ldg(bc);

    // layer 0: y0 = s*a0 + c0 ; y1 = s*a1 + c1
    const float a0 = __ldg(Wl + 0);            // W0[0][0]
    const float a1 = __ldg(Wl + 2);            // W0[1][0]
    const float c0 = __ldg(bl + 0);
    const float c1 = __ldg(bl + 1);

    // hidden layers 1..4 folded: y_i = t0*w[i0] + t1*w[i1] + bb[i]
    float w00[4], w01[4], w10[4], w11[4], bb0[4], bb1[4];
#pragma unroll
    for (int l = 1; l < 5; l++) {
        const float sc0 = __ldg(scale + 2 * (l - 1) + 0);
        const float sc1 = __ldg(scale + 2 * (l - 1) + 1);
        const float sh0 = __ldg(shift + 2 * (l - 1) + 0);
        const float sh1 = __ldg(shift + 2 * (l - 1) + 1);
        const float W00 = __ldg(Wl + 4 * l + 0);
        const float W01 = __ldg(Wl + 4 * l + 1);
        const float W10 = __ldg(Wl + 4 * l + 2);
        const float W11 = __ldg(Wl + 4 * l + 3);
        const int j = l - 1;
        w00[j] = W00 * sc0;  w01[j] = W01 * sc1;
        w10[j] = W10 * sc0;  w11[j] = W11 * sc1;
        bb0[j] = fmaf(W00, sh0, fmaf(W01, sh1, __ldg(bl + 2 * l + 0)));
        bb1[j] = fmaf(W10, sh0, fmaf(W11, sh1, __ldg(bl + 2 * l + 1)));
    }

    // final: out = t0*wf0 + t1*wf1 + bfv  (folds scale/shift of layer 4)
    const float Wf0 = __ldg(Wf + 0), Wf1 = __ldg(Wf + 1);
    const float sc40 = __ldg(scale + 8), sc41 = __ldg(scale + 9);
    const float sh40 = __ldg(shift + 8), sh41 = __ldg(shift + 9);
    const float wf0 = Wf0 * sc40;
    const float wf1 = Wf1 * sc41;
    const float bfv = fmaf(Wf0, sh40, fmaf(Wf1, sh41, __ldg(bf)));

    // ================= batched load -> compute -> store =================
    const int base = blockIdx.x * (THREADS * PPT) + threadIdx.x;

    float4 d[PPT];
#pragma unroll
    for (int k = 0; k < PPT; k++) {
        const int i = base + k * THREADS;
        if (i < B) d[k] = __ldcs(data + i);   // 8 independent LDG.128 -> MLP=8
    }

#pragma unroll
    for (int k = 0; k < PPT; k++) {
        const int i = base + k * THREADS;
        if (i >= B) continue;

        // conv-as-dot + bias, sigmoid
        const float z = fmaf(d[k].x, wc0, fmaf(d[k].y, wc1,
                        fmaf(d[k].z, wc2, fmaf(d[k].w, wc3, bcv))));
        const float s = fast_sigmoid(z);

        // layer 0
        float t0 = fast_tanh(fmaf(s, a0, c0));
        float t1 = fast_tanh(fmaf(s, a1, c1));

        // layers 1..4 (folded)
#pragma unroll
        for (int j = 0; j < 4; j++) {
            const float y0 = fmaf(t0, w00[j], fmaf(t1, w01[j], bb0[j]));
            const float y1 = fmaf(t0, w10[j], fmaf(t1, w11[j], bb1[j]));
            t0 = fast_tanh(y0);
            t1 = fast_tanh(y1);
        }

        const float o = fmaf(t0, wf0, fmaf(t1, wf1, bfv));
        __stcs(out + i, o);
    }
}

extern "C" void kernel_launch(void* const* d_in, const int* in_sizes, int n_in,
                              void* d_out, int out_size)
{
    const float4* data  = (const float4*)d_in[0];
    const float*  Wc    = (const float*)d_in[1];
    const float*  bc    = (const float*)d_in[2];
    const float*  Wl    = (const float*)d_in[3];
    const float*  bl    = (const float*)d_in[4];
    const float*  scale = (const float*)d_in[5];
    const float*  shift = (const float*)d_in[6];
    const float*  Wf    = (const float*)d_in[7];
    const float*  bf    = (const float*)d_in[8];
    float* out = (float*)d_out;

    const int B = in_sizes[0] / 4;          // 4 floats per patch

    const int per_block = THREADS * PPT;
    int blocks = (B + per_block - 1) / per_block;
    if (blocks < 1) blocks = 1;

    fraud_kernel<<<blocks, THREADS>>>(data, Wc, bc, Wl, bl, scale, shift, Wf, bf, out, B);
}

// round 3
// speedup vs baseline: 2.1894x; 1.7273x over previous
#include <cuda_runtime.h>
#include <math.h>

#define TBL 4096
#define THREADS 256
#define CHUNK 8          // patches per thread per chunk (MLP depth)
#define NCHUNK 4         // chunks per thread
#define PER_BLOCK (THREADS * CHUNK * NCHUNK)   // 8192 patches per block

// Table of the scalar chain F(s), s in [0,1]:  entry i = { F(i/TBL), F((i+1)/TBL)-F(i/TBL) }
__device__ float2 d_tab[TBL];

// ---------------- Kernel 1: tabulate F(s) with accurate tanhf ----------------
__device__ __forceinline__ float eval_chain(float s,
                                            const float* __restrict__ Wl,
                                            const float* __restrict__ bl,
                                            const float* __restrict__ scale,
                                            const float* __restrict__ shift,
                                            const float* __restrict__ Wf,
                                            const float* __restrict__ bf)
{
    float x0 = s, x1 = 0.0f;
#pragma unroll
    for (int l = 0; l < 5; l++) {
        float y0 = tanhf(fmaf(x0, __ldg(Wl + 4 * l + 0), fmaf(x1, __ldg(Wl + 4 * l + 1), __ldg(bl + 2 * l + 0))));
        float y1 = tanhf(fmaf(x0, __ldg(Wl + 4 * l + 2), fmaf(x1, __ldg(Wl + 4 * l + 3), __ldg(bl + 2 * l + 1))));
        x0 = fmaf(y0, __ldg(scale + 2 * l + 0), __ldg(shift + 2 * l + 0));
        x1 = fmaf(y1, __ldg(scale + 2 * l + 1), __ldg(shift + 2 * l + 1));
    }
    return fmaf(x0, __ldg(Wf + 0), fmaf(x1, __ldg(Wf + 1), __ldg(bf)));
}

__global__ void tab_kernel(const float* __restrict__ Wl, const float* __restrict__ bl,
                           const float* __restrict__ scale, const float* __restrict__ shift,
                           const float* __restrict__ Wf, const float* __restrict__ bf)
{
    int j = blockIdx.x * blockDim.x + threadIdx.x;
    if (j >= TBL) return;
    const float inv = 1.0f / (float)TBL;
    float v0 = eval_chain((float)j * inv,       Wl, bl, scale, shift, Wf, bf);
    float v1 = eval_chain((float)(j + 1) * inv, Wl, bl, scale, shift, Wf, bf);
    d_tab[j] = make_float2(v0, v1 - v0);
}

// ---------------- Kernel 2: streaming conv + sigmoid + table lerp ----------------
__global__ __launch_bounds__(THREADS)
void fraud_kernel(const float4* __restrict__ data,
                  const float* __restrict__ Wc, const float* __restrict__ bc,
                  float* __restrict__ out, int B)
{
    __shared__ float2 tab[TBL];

    // cooperative table load (32KB, L2-hot after first block)
    {
        const float4* src = (const float4*)d_tab;
        float4* dst = (float4*)tab;
#pragma unroll
        for (int i = threadIdx.x; i < TBL / 2; i += THREADS) dst[i] = src[i];
    }

    // fold -log2(e) into conv weights:  s = 1/(1 + 2^(z'))  with z' = -log2(e)*(conv+bias)
    const float NL2E = -1.4426950408889634f;
    const float wc0 = __ldg(Wc + 0) * NL2E, wc1 = __ldg(Wc + 1) * NL2E;
    const float wc2 = __ldg(Wc + 2) * NL2E, wc3 = __ldg(Wc + 3) * NL2E;
    const float bcv = __ldg(bc) * NL2E;

    __syncthreads();

#pragma unroll
    for (int c = 0; c < NCHUNK; c++) {
        const int base = blockIdx.x * PER_BLOCK + c * (THREADS * CHUNK) + threadIdx.x;

        float4 d[CHUNK];
#pragma unroll
        for (int k = 0; k < CHUNK; k++) {
            const int i = base + k * THREADS;
            if (i < B) d[k] = __ldcs(data + i);   // independent LDG.128, MLP=8
        }

#pragma unroll
        for (int k = 0; k < CHUNK; k++) {
            const int i = base + k * THREADS;
            if (i >= B) continue;

            const float zp = fmaf(d[k].x, wc0, fmaf(d[k].y, wc1,
                             fmaf(d[k].z, wc2, fmaf(d[k].w, wc3, bcv))));
            float e;
            asm("ex2.approx.f32 %0, %1;" : "=f"(e) : "f"(zp));
            float s;
            asm("rcp.approx.f32 %0, %1;" : "=f"(s) : "f"(e + 1.0f));

            float t = s * (float)TBL;            // t in [0, TBL]
            int idx = (int)t;
            idx = min(idx, TBL - 1);
            const float f = t - (float)idx;
            const float2 v = tab[idx];
            __stcs(out + i, fmaf(v.y, f, v.x));
        }
    }
}

extern "C" void kernel_launch(void* const* d_in, const int* in_sizes, int n_in,
                              void* d_out, int out_size)
{
    const float4* data  = (const float4*)d_in[0];
    const float*  Wc    = (const float*)d_in[1];
    const float*  bc    = (const float*)d_in[2];
    const float*  Wl    = (const float*)d_in[3];
    const float*  bl    = (const float*)d_in[4];
    const float*  scale = (const float*)d_in[5];
    const float*  shift = (const float*)d_in[6];
    const float*  Wf    = (const float*)d_in[7];
    const float*  bf    = (const float*)d_in[8];
    float* out = (float*)d_out;

    const int B = in_sizes[0] / 4;          // 4 floats per patch

    tab_kernel<<<TBL / 128, 128>>>(Wl, bl, scale, shift, Wf, bf);

    int blocks = (B + PER_BLOCK - 1) / PER_BLOCK;
    if (blocks < 1) blocks = 1;
    fraud_kernel<<<blocks, THREADS>>>(data, Wc, bc, out, B);
}

// round 4
// speedup vs baseline: 2.4492x; 1.1186x over previous
#include <cuda_runtime.h>
#include <math.h>

#define TBL 1024
#define THREADS 256
#define CHUNK 8          // patches per thread per chunk (MLP depth)
#define NCHUNK 2         // chunks per thread
#define PER_BLOCK (THREADS * CHUNK * NCHUNK)   // 4096 patches per block

// Table of the scalar chain F(s), s in [0,1]:  entry i = { F(i/TBL), F((i+1)/TBL)-F(i/TBL) }
__device__ float2 d_tab[TBL];

// ---------------- Kernel 1: tabulate F(s) with accurate tanhf ----------------
__device__ __forceinline__ float eval_chain(float s,
                                            const float* __restrict__ Wl,
                                            const float* __restrict__ bl,
                                            const float* __restrict__ scale,
                                            const float* __restrict__ shift,
                                            const float* __restrict__ Wf,
                                            const float* __restrict__ bf)
{
    float x0 = s, x1 = 0.0f;
#pragma unroll
    for (int l = 0; l < 5; l++) {
        float y0 = tanhf(fmaf(x0, __ldg(Wl + 4 * l + 0), fmaf(x1, __ldg(Wl + 4 * l + 1), __ldg(bl + 2 * l + 0))));
        float y1 = tanhf(fmaf(x0, __ldg(Wl + 4 * l + 2), fmaf(x1, __ldg(Wl + 4 * l + 3), __ldg(bl + 2 * l + 1))));
        x0 = fmaf(y0, __ldg(scale + 2 * l + 0), __ldg(shift + 2 * l + 0));
        x1 = fmaf(y1, __ldg(scale + 2 * l + 1), __ldg(shift + 2 * l + 1));
    }
    return fmaf(x0, __ldg(Wf + 0), fmaf(x1, __ldg(Wf + 1), __ldg(bf)));
}

__global__ void tab_kernel(const float* __restrict__ Wl, const float* __restrict__ bl,
                           const float* __restrict__ scale, const float* __restrict__ shift,
                           const float* __restrict__ Wf, const float* __restrict__ bf)
{
    int j = blockIdx.x * blockDim.x + threadIdx.x;
    if (j >= TBL) return;
    const float inv = 1.0f / (float)TBL;
    float v0 = eval_chain((float)j * inv,       Wl, bl, scale, shift, Wf, bf);
    float v1 = eval_chain((float)(j + 1) * inv, Wl, bl, scale, shift, Wf, bf);
    d_tab[j] = make_float2(v0, v1 - v0);
}

// ---------------- Kernel 2: streaming conv + sigmoid + table lerp ----------------
__global__ __launch_bounds__(THREADS)
void fraud_kernel(const float4* __restrict__ data,
                  const float* __restrict__ Wc, const float* __restrict__ bc,
                  float* __restrict__ out, int B)
{
    __shared__ float2 tab[TBL];   // 8 KB -> occupancy limited by regs, ~5 CTAs/SM

    // cooperative table load (8KB: 2 float4 per thread, L2-hot after first wave)
    {
        const float4* src = (const float4*)d_tab;
        float4* dst = (float4*)tab;
#pragma unroll
        for (int i = threadIdx.x; i < TBL / 2; i += THREADS) dst[i] = src[i];
    }

    // fold -log2(e) into conv weights:  s = 1/(1 + 2^(z'))  with z' = -log2(e)*(conv+bias)
    const float NL2E = -1.4426950408889634f;
    const float wc0 = __ldg(Wc + 0) * NL2E, wc1 = __ldg(Wc + 1) * NL2E;
    const float wc2 = __ldg(Wc + 2) * NL2E, wc3 = __ldg(Wc + 3) * NL2E;
    const float bcv = __ldg(bc) * NL2E;

    __syncthreads();

#pragma unroll
    for (int c = 0; c < NCHUNK; c++) {
        const int base = blockIdx.x * PER_BLOCK + c * (THREADS * CHUNK) + threadIdx.x;

        float4 d[CHUNK];
#pragma unroll
        for (int k = 0; k < CHUNK; k++) {
            const int i = base + k * THREADS;
            if (i < B) d[k] = __ldcs(data + i);   // independent LDG.128, MLP=8
        }

#pragma unroll
        for (int k = 0; k < CHUNK; k++) {
            const int i = base + k * THREADS;
            if (i >= B) continue;

            const float zp = fmaf(d[k].x, wc0, fmaf(d[k].y, wc1,
                             fmaf(d[k].z, wc2, fmaf(d[k].w, wc3, bcv))));
            float e;
            asm("ex2.approx.f32 %0, %1;" : "=f"(e) : "f"(zp));
            float s;
            asm("rcp.approx.f32 %0, %1;" : "=f"(s) : "f"(e + 1.0f));

            float t = s * (float)TBL;            // t in [0, TBL]
            int idx = (int)t;
            idx = min(idx, TBL - 1);
            const float f = t - (float)idx;
            const float2 v = tab[idx];
            __stcs(out + i, fmaf(v.y, f, v.x));
        }
    }
}

extern "C" void kernel_launch(void* const* d_in, const int* in_sizes, int n_in,
                              void* d_out, int out_size)
{
    const float4* data  = (const float4*)d_in[0];
    const float*  Wc    = (const float*)d_in[1];
    const float*  bc    = (const float*)d_in[2];
    const float*  Wl    = (const float*)d_in[3];
    const float*  bl    = (const float*)d_in[4];
    const float*  scale = (const float*)d_in[5];
    const float*  shift = (const float*)d_in[6];
    const float*  Wf    = (const float*)d_in[7];
    const float*  bf    = (const float*)d_in[8];
    float* out = (float*)d_out;

    const int B = in_sizes[0] / 4;          // 4 floats per patch

    tab_kernel<<<TBL / 128, 128>>>(Wl, bl, scale, shift, Wf, bf);

    int blocks = (B + PER_BLOCK - 1) / PER_BLOCK;
    if (blocks < 1) blocks = 1;
    fraud_kernel<<<blocks, THREADS>>>(data, Wc, bc, out, B);
}